// round 8
// baseline (speedup 1.0000x reference)
#include <cuda_runtime.h>
#include <cuda_bf16.h>
#include <math.h>
#include <stdint.h>

#define BB 8
#define SS 512
#define DD 768
#define HH 12
#define LL 12
#define DH 64
#define DF 3072
#define VV 40478
#define MTOK (BB*SS)

#define K3_D  (3*DD)       // 2304
#define K3_F  (3*DF)       // 9216

#define WQ_ELEMS ((size_t)(3*DD) * K3_D)
#define WP_ELEMS ((size_t)DD * K3_D)
#define WF_ELEMS ((size_t)DF * K3_D)
#define WR_ELEMS ((size_t)DD * K3_F)
#define WL_ELEMS (WQ_ELEMS + WP_ELEMS + WF_ELEMS + WR_ELEMS)
#define OFF_Q 0
#define OFF_P (WQ_ELEMS)
#define OFF_F (WQ_ELEMS + WP_ELEMS)
#define OFF_R (WQ_ELEMS + WP_ELEMS + WF_ELEMS)

// ---------------- static scratch ----------------
__device__ __align__(1024) float g_h[MTOK * DD];
__device__ __align__(1024) float g_qkv[MTOK * 3 * DD];
__device__ __align__(1024) float g_attn[MTOK * DD];
__device__ __align__(1024) float g_tmp[MTOK * DD];
__device__ __align__(1024) float g_mid[MTOK * DF];
__device__ __align__(1024) __nv_bfloat16 g_wexp[12 * WL_ELEMS];

// ---------------- PTX helpers (generic sm_80+ only) ----------------
__device__ __forceinline__ uint32_t smem_u32(const void* p) {
    uint32_t a;
    asm("{ .reg .u64 t; cvta.to.shared.u64 t, %1; cvt.u32.u64 %0, t; }"
        : "=r"(a) : "l"(p));
    return a;
}
__device__ __forceinline__ void cp16(uint32_t dst, const void* src) {
    asm volatile("cp.async.cg.shared.global [%0], [%1], 16;" :: "r"(dst), "l"(src));
}
__device__ __forceinline__ void cp_commit() {
    asm volatile("cp.async.commit_group;" ::);
}
template<int N>
__device__ __forceinline__ void cp_wait() {
    asm volatile("cp.async.wait_group %0;" :: "n"(N));
}
__device__ __forceinline__ void mma16816(float* c, const uint32_t* a, const uint32_t* b) {
    asm volatile(
        "mma.sync.aligned.m16n8k16.row.col.f32.bf16.bf16.f32 "
        "{%0,%1,%2,%3}, {%4,%5,%6,%7}, {%8,%9}, {%0,%1,%2,%3};"
        : "+f"(c[0]), "+f"(c[1]), "+f"(c[2]), "+f"(c[3])
        : "r"(a[0]), "r"(a[1]), "r"(a[2]), "r"(a[3]), "r"(b[0]), "r"(b[1]));
}
__device__ __forceinline__ void ldm_x4(uint32_t* r, uint32_t addr) {
    asm volatile("ldmatrix.sync.aligned.m8n8.x4.shared.b16 {%0,%1,%2,%3}, [%4];"
                 : "=r"(r[0]), "=r"(r[1]), "=r"(r[2]), "=r"(r[3]) : "r"(addr));
}

__device__ __forceinline__ float gelu_f(float x) {
    const float c = 0.7978845608028654f;
    float x3 = x * x * x;
    return 0.5f * x * (1.0f + tanhf(c * (x + 0.044715f * x3)));
}

// ---------------- embedding ----------------
__global__ void embed_kernel(const int* __restrict__ tokens,
                             const float* __restrict__ we,
                             float* __restrict__ h)
{
    int t = blockIdx.x;
    int s = t % SS;
    int tok = tokens[t];
    const float* wrow = we + (size_t)tok * DD;
    const float* prow = we + (size_t)(VV + s) * DD;
    float* hrow = h + (size_t)t * DD;
    for (int i = threadIdx.x; i < DD; i += blockDim.x)
        hrow[i] = wrow[i] + prow[i];
}

// --------- weight transpose + split: W[K,N] -> We[N,3K] = [hi|hi|lo] --------
__global__ __launch_bounds__(256)
void wexpand(const float* __restrict__ W, __nv_bfloat16* __restrict__ We,
             int K, int N)
{
    __shared__ float t[32][33];
    const int n0 = blockIdx.x * 32;
    const int k0 = blockIdx.y * 32;
    const int tx = threadIdx.x & 31;
    const int ty = threadIdx.x >> 5;
    for (int r = ty; r < 32; r += 8)
        t[r][tx] = W[(size_t)(k0 + r) * N + n0 + tx];
    __syncthreads();
    for (int r = ty; r < 32; r += 8) {
        int n = n0 + r, k = k0 + tx;
        float v = t[tx][r];
        __nv_bfloat16 hi = __float2bfloat16(v);
        float lo = v - __bfloat162float(hi);
        size_t ro = (size_t)n * (3 * K);
        We[ro + k]         = hi;
        We[ro + K + k]     = hi;
        We[ro + 2 * K + k] = __float2bfloat16(lo);
    }
}

// ---------------- fused split-bf16 mma GEMM --------------------------------
// C[M,N] = X[M,K](fp32, split on the fly to [hi|lo|hi]) @ B[N,3K]^T + bias.
// 128x128 tile, K3-chunks of 32, 4-stage pipeline (A: LDG+convert+STS 1 iter
// ahead; B: cp.async 3 ahead), 8 warps (4M x 2N), ldmatrix fragment loads.
#define MSTAGES 4
#define APAD 40
#define ASTG (128 * APAD)              // elems per tile region = 5120
#define STG_ELEMS (2 * ASTG)
#define GEMM_SMEM (MSTAGES * STG_ELEMS * 2)   // 81920 bytes

__global__ __launch_bounds__(256, 2)
void gemm_mma(const float* __restrict__ A, const __nv_bfloat16* __restrict__ B,
              const float* __restrict__ bias, float* __restrict__ C,
              int N, int K, int act)
{
    extern __shared__ __nv_bfloat16 sh[];
    const int tid  = threadIdx.x;
    const int wid  = tid >> 5;
    const int lane = tid & 31;
    const int m0 = blockIdx.y * 128;
    const int n0 = blockIdx.x * 128;
    const int wm = (wid & 3) * 32;
    const int wn = (wid >> 2) * 64;
    const int K3 = 3 * K;
    const int nk = K3 >> 5;

    const float* Af = A + (size_t)m0 * K;
    const __nv_bfloat16* Bb = B + (size_t)n0 * K3;

    // B cp.async slots: 2 x 16B per thread per stage (8KB tile)
    const int id0 = tid * 2, id1 = tid * 2 + 1;
    const int rb0 = id0 >> 2, cb0 = (id0 & 3) * 8;
    const int rb1 = id1 >> 2, cb1 = (id1 & 3) * 8;

    auto issueB = [&](int kc) {
        __nv_bfloat16* Sb = sh + (kc & 3) * STG_ELEMS + ASTG;
        const __nv_bfloat16* gb = Bb + (size_t)kc * 32;
        cp16(smem_u32(Sb + rb0 * APAD + cb0), gb + (size_t)rb0 * K3 + cb0);
        cp16(smem_u32(Sb + rb1 * APAD + cb1), gb + (size_t)rb1 * K3 + cb1);
        cp_commit();
    };

    // A slots: 4 x float4 per thread (128x32 fp32 tile)
    int rA[4], cA[4];
    #pragma unroll
    for (int i = 0; i < 4; i++) {
        int idx = tid + i * 256;
        rA[i] = idx >> 3; cA[i] = (idx & 7) * 4;
    }
    float4 pa[4];
    auto ldA = [&](int kc) {
        const int col0 = (kc * 32) % K;
        #pragma unroll
        for (int i = 0; i < 4; i++)
            pa[i] = *(const float4*)(Af + (size_t)rA[i] * K + col0 + cA[i]);
    };
    auto stsA = [&](int kc) {
        const int seg = (kc * 32) / K;     // 0:hi 1:lo 2:hi
        __nv_bfloat16* Sa = sh + (kc & 3) * STG_ELEMS;
        #pragma unroll
        for (int i = 0; i < 4; i++) {
            float4 v = pa[i];
            if (seg == 1) {
                v.x -= __bfloat162float(__float2bfloat16(v.x));
                v.y -= __bfloat162float(__float2bfloat16(v.y));
                v.z -= __bfloat162float(__float2bfloat16(v.z));
                v.w -= __bfloat162float(__float2bfloat16(v.w));
            }
            __nv_bfloat162 h0 = __floats2bfloat162_rn(v.x, v.y);
            __nv_bfloat162 h1 = __floats2bfloat162_rn(v.z, v.w);
            uint2 w;
            w.x = *reinterpret_cast<uint32_t*>(&h0);
            w.y = *reinterpret_cast<uint32_t*>(&h1);
            *reinterpret_cast<uint2*>(Sa + rA[i] * APAD + cA[i]) = w;
        }
    };

    float acc[2][8][4];
    #pragma unroll
    for (int mt = 0; mt < 2; mt++)
        #pragma unroll
        for (int nt = 0; nt < 8; nt++)
            #pragma unroll
            for (int i = 0; i < 4; i++) acc[mt][nt][i] = 0.0f;

    // prologue
    issueB(0); issueB(1); issueB(2);
    ldA(0); stsA(0);
    ldA(1);
    cp_wait<2>();
    __syncthreads();

    for (int kc = 0; kc < nk; kc++) {
        if (kc + 1 < nk) stsA(kc + 1);
        if (kc + 2 < nk) ldA(kc + 2);
        if (kc + 3 < nk) issueB(kc + 3);

        const __nv_bfloat16* Sa = sh + (kc & 3) * STG_ELEMS;
        const __nv_bfloat16* Sb = Sa + ASTG;
        #pragma unroll
        for (int ks = 0; ks < 2; ks++) {
            const int kb = ks * 16;
            uint32_t af[2][4], bfr[8][2];
            #pragma unroll
            for (int mt = 0; mt < 2; mt++) {
                int row = wm + mt * 16 + (lane & 7) + ((lane >> 3) & 1) * 8;
                int col = kb + (lane >> 4) * 8;
                ldm_x4(af[mt], smem_u32(Sa + row * APAD + col));
            }
            #pragma unroll
            for (int np = 0; np < 4; np++) {
                int nt0 = np * 2;
                int row = wn + (nt0 + (lane >> 4)) * 8 + (lane & 7);
                int col = kb + ((lane >> 3) & 1) * 8;
                uint32_t r4[4];
                ldm_x4(r4, smem_u32(Sb + row * APAD + col));
                bfr[nt0][0] = r4[0]; bfr[nt0][1] = r4[1];
                bfr[nt0 + 1][0] = r4[2]; bfr[nt0 + 1][1] = r4[3];
            }
            #pragma unroll
            for (int mt = 0; mt < 2; mt++)
                #pragma unroll
                for (int nt = 0; nt < 8; nt++)
                    mma16816(acc[mt][nt], af[mt], bfr[nt]);
        }
        if (kc + 1 < nk) { cp_wait<2>(); __syncthreads(); }
    }

    // epilogue
    #pragma unroll
    for (int mt = 0; mt < 2; mt++) {
        const int r = m0 + wm + mt * 16 + (lane >> 2);
        #pragma unroll
        for (int nt = 0; nt < 8; nt++) {
            const int c = n0 + wn + nt * 8 + (lane & 3) * 2;
            const float b0 = bias[c], b1 = bias[c + 1];
            float v0 = acc[mt][nt][0] + b0;
            float v1 = acc[mt][nt][1] + b1;
            float v2 = acc[mt][nt][2] + b0;
            float v3 = acc[mt][nt][3] + b1;
            if (act) { v0 = gelu_f(v0); v1 = gelu_f(v1); v2 = gelu_f(v2); v3 = gelu_f(v3); }
            *(float2*)(C + (size_t)r * N + c)       = make_float2(v0, v1);
            *(float2*)(C + (size_t)(r + 8) * N + c) = make_float2(v2, v3);
        }
    }
}

// ---------------- flash attention (SIMT fp32) -----------------------------
#define ASTR_Q 132
#define ASTR_K 68
#define ATTN_FLOATS (64*ASTR_Q + 64*ASTR_K + 64*ASTR_K + 128*ASTR_K + 128 + 128 + 128*17)
#define ATTN_DSMEM (ATTN_FLOATS * 4)

__global__ __launch_bounds__(256)
void attn_flash(const float* __restrict__ qkv, float* __restrict__ out)
{
    extern __shared__ float af[];
    float* Qs   = af;
    float* Ks   = Qs + 64 * ASTR_Q;
    float* Vs   = Ks + 64 * ASTR_K;
    float* Ps   = Vs + 64 * ASTR_K;
    float* mrow = Ps + 128 * ASTR_K;
    float* lrow = mrow + 128;
    float* red  = lrow + 128;

    const int tid = threadIdx.x;
    const int tx = tid & 15;
    const int ty = tid >> 4;
    const int q0 = ty * 8;
    const int k0 = tx * 4;
    const int qt = blockIdx.x;
    const int h  = blockIdx.y;
    const int b  = blockIdx.z;
    const float* base = qkv + (size_t)b * SS * (3 * DD);

    for (int i = tid; i < 128 * 16; i += 256) {
        int q = i >> 4, d = (i & 15) * 4;
        float4 v = *(const float4*)(base + (size_t)(qt * 128 + q) * (3 * DD) + h * 64 + d);
        Qs[(d + 0) * ASTR_Q + q] = v.x * 0.125f;
        Qs[(d + 1) * ASTR_Q + q] = v.y * 0.125f;
        Qs[(d + 2) * ASTR_Q + q] = v.z * 0.125f;
        Qs[(d + 3) * ASTR_Q + q] = v.w * 0.125f;
    }
    if (tid < 128) { mrow[tid] = -1e30f; lrow[tid] = 0.0f; }

    float Oacc[8][4];
    #pragma unroll
    for (int i = 0; i < 8; i++)
        #pragma unroll
        for (int j = 0; j < 4; j++) Oacc[i][j] = 0.0f;

    const int nkt = (qt + 1) * 2;
    for (int kt = 0; kt < nkt; kt++) {
        __syncthreads();
        for (int i = tid; i < 64 * 16; i += 256) {
            int kk = i >> 4, d = (i & 15) * 4;
            const float* kp = base + (size_t)(kt * 64 + kk) * (3 * DD) + DD + h * 64 + d;
            float4 v = *(const float4*)kp;
            Ks[(d + 0) * ASTR_K + kk] = v.x;
            Ks[(d + 1) * ASTR_K + kk] = v.y;
            Ks[(d + 2) * ASTR_K + kk] = v.z;
            Ks[(d + 3) * ASTR_K + kk] = v.w;
            const float* vp = base + (size_t)(kt * 64 + kk) * (3 * DD) + 2 * DD + h * 64 + d;
            *(float4*)(Vs + kk * ASTR_K + d) = *(const float4*)vp;
        }
        __syncthreads();

        float s[8][4];
        #pragma unroll
        for (int i = 0; i < 8; i++)
            #pragma unroll
            for (int j = 0; j < 4; j++) s[i][j] = 0.0f;

        for (int d = 0; d < 64; d++) {
            float4 kv = *(const float4*)(Ks + d * ASTR_K + k0);
            float4 qa = *(const float4*)(Qs + d * ASTR_Q + q0);
            float4 qb = *(const float4*)(Qs + d * ASTR_Q + q0 + 4);
            float qv[8] = {qa.x, qa.y, qa.z, qa.w, qb.x, qb.y, qb.z, qb.w};
            float kk[4] = {kv.x, kv.y, kv.z, kv.w};
            #pragma unroll
            for (int i = 0; i < 8; i++)
                #pragma unroll
                for (int j = 0; j < 4; j++)
                    s[i][j] = fmaf(qv[i], kk[j], s[i][j]);
        }

        if (kt >= 2 * qt) {
            const int diag = (kt - 2 * qt) * 64;
            #pragma unroll
            for (int i = 0; i < 8; i++)
                #pragma unroll
                for (int j = 0; j < 4; j++)
                    if (q0 + i < diag + k0 + j) s[i][j] = -1e9f;
        }

        #pragma unroll
        for (int i = 0; i < 8; i++) {
            float m4 = fmaxf(fmaxf(s[i][0], s[i][1]), fmaxf(s[i][2], s[i][3]));
            red[(q0 + i) * 17 + tx] = m4;
        }
        __syncthreads();
        if (tid < 128) {
            float m = mrow[tid];
            float mn = m;
            #pragma unroll
            for (int t = 0; t < 16; t++) mn = fmaxf(mn, red[tid * 17 + t]);
            red[tid * 17 + 16] = __expf(m - mn);
            mrow[tid] = mn;
        }
        __syncthreads();

        #pragma unroll
        for (int i = 0; i < 8; i++) {
            float m = mrow[q0 + i];
            float ps = 0.0f;
            #pragma unroll
            for (int j = 0; j < 4; j++) {
                float p = __expf(s[i][j] - m);
                Ps[(q0 + i) * ASTR_K + k0 + j] = p;
                ps += p;
            }
            red[(q0 + i) * 17 + tx] = ps;
        }
        __syncthreads();
        if (tid < 128) {
            float ssum = 0.0f;
            #pragma unroll
            for (int t = 0; t < 16; t++) ssum += red[tid * 17 + t];
            lrow[tid] = lrow[tid] * red[tid * 17 + 16] + ssum;
        }

        #pragma unroll
        for (int i = 0; i < 8; i++) {
            float a = red[(q0 + i) * 17 + 16];
            #pragma unroll
            for (int j = 0; j < 4; j++) Oacc[i][j] *= a;
        }
        for (int k = 0; k < 64; k++) {
            float4 vv = *(const float4*)(Vs + k * ASTR_K + k0);
            float vr[4] = {vv.x, vv.y, vv.z, vv.w};
            #pragma unroll
            for (int i = 0; i < 8; i++) {
                float p = Ps[(q0 + i) * ASTR_K + k];
                #pragma unroll
                for (int j = 0; j < 4; j++)
                    Oacc[i][j] = fmaf(p, vr[j], Oacc[i][j]);
            }
        }
    }
    __syncthreads();

    #pragma unroll
    for (int i = 0; i < 8; i++) {
        float inv = 1.0f / lrow[q0 + i];
        float4 o = make_float4(Oacc[i][0] * inv, Oacc[i][1] * inv,
                               Oacc[i][2] * inv, Oacc[i][3] * inv);
        *(float4*)(out + (size_t)(b * SS + qt * 128 + q0 + i) * DD + h * 64 + k0) = o;
    }
}

// ---------------- fused residual add + LayerNorm --------------------------
__global__ __launch_bounds__(256)
void add_ln_kernel(const float* __restrict__ x, const float* __restrict__ a,
                   const float* __restrict__ g, const float* __restrict__ bb,
                   float* __restrict__ out)
{
    const int row = blockIdx.x;
    const int tid = threadIdx.x;
    __shared__ float red[256];

    const size_t off = (size_t)row * DD;
    float v[3];
    float s = 0.0f;
    #pragma unroll
    for (int i = 0; i < 3; i++) {
        int c = tid + 256 * i;
        v[i] = x[off + c] + a[off + c];
        s += v[i];
    }
    red[tid] = s; __syncthreads();
    for (int st = 128; st > 0; st >>= 1) {
        if (tid < st) red[tid] += red[tid + st];
        __syncthreads();
    }
    const float mean = red[0] * (1.0f / DD);
    __syncthreads();

    float s2 = 0.0f;
    #pragma unroll
    for (int i = 0; i < 3; i++) {
        float d = v[i] - mean;
        s2 += d * d;
    }
    red[tid] = s2; __syncthreads();
    for (int st = 128; st > 0; st >>= 1) {
        if (tid < st) red[tid] += red[tid + st];
        __syncthreads();
    }
    const float inv = rsqrtf(red[0] * (1.0f / DD) + 1e-5f);

    #pragma unroll
    for (int i = 0; i < 3; i++) {
        int c = tid + 256 * i;
        out[off + c] = g[c] * (v[i] - mean) * inv + bb[c];
    }
}

// ---------------- launch ----------------
extern "C" void kernel_launch(void* const* d_in, const int* in_sizes, int n_in,
                              void* d_out, int out_size)
{
    const int*   tokens = (const int*)  d_in[0];
    const float* we     = (const float*)d_in[1];
    const float* wqkv   = (const float*)d_in[2];
    const float* bqkv   = (const float*)d_in[3];
    const float* wproj  = (const float*)d_in[4];
    const float* bproj  = (const float*)d_in[5];
    const float* g1     = (const float*)d_in[6];
    const float* b1     = (const float*)d_in[7];
    const float* wfc    = (const float*)d_in[8];
    const float* bfc    = (const float*)d_in[9];
    const float* wpr    = (const float*)d_in[10];
    const float* bpr    = (const float*)d_in[11];
    const float* g2     = (const float*)d_in[12];
    const float* b2     = (const float*)d_in[13];
    float* out = (float*)d_out;

    float *h, *qkv, *attn, *tmp, *mid;
    __nv_bfloat16 *wex;
    cudaGetSymbolAddress((void**)&h,    g_h);
    cudaGetSymbolAddress((void**)&qkv,  g_qkv);
    cudaGetSymbolAddress((void**)&attn, g_attn);
    cudaGetSymbolAddress((void**)&tmp,  g_tmp);
    cudaGetSymbolAddress((void**)&mid,  g_mid);
    cudaGetSymbolAddress((void**)&wex,  g_wexp);

    cudaFuncSetAttribute(gemm_mma, cudaFuncAttributeMaxDynamicSharedMemorySize, GEMM_SMEM);
    cudaFuncSetAttribute(attn_flash, cudaFuncAttributeMaxDynamicSharedMemorySize, ATTN_DSMEM);

    // expand all weights (transposed, split-bf16)
    for (int l = 0; l < LL; l++) {
        __nv_bfloat16* wl = wex + (size_t)l * WL_ELEMS;
        wexpand<<<dim3(3*DD/32, DD/32), 256>>>(wqkv  + (size_t)l*DD*3*DD, wl + OFF_Q, DD, 3*DD);
        wexpand<<<dim3(DD/32,   DD/32), 256>>>(wproj + (size_t)l*DD*DD,   wl + OFF_P, DD, DD);
        wexpand<<<dim3(DF/32,   DD/32), 256>>>(wfc   + (size_t)l*DD*DF,   wl + OFF_F, DD, DF);
        wexpand<<<dim3(DD/32,   DF/32), 256>>>(wpr   + (size_t)l*DF*DD,   wl + OFF_R, DF, DD);
    }

    embed_kernel<<<MTOK, 256>>>(tokens, we, h);

    for (int l = 0; l < LL; l++) {
        const __nv_bfloat16* wl = wex + (size_t)l * WL_ELEMS;
        const float* bq = bqkv  + (size_t)l * 3 * DD;
        const float* bp = bproj + (size_t)l * DD;
        const float* gA = g1 + (size_t)l * DD;
        const float* bA = b1 + (size_t)l * DD;
        const float* bf = bfc + (size_t)l * DF;
        const float* br = bpr + (size_t)l * DD;
        const float* gB = g2 + (size_t)l * DD;
        const float* bB = b2 + (size_t)l * DD;

        gemm_mma<<<dim3(3*DD/128, MTOK/128), 256, GEMM_SMEM>>>(
            h, wl + OFF_Q, bq, qkv, 3*DD, DD, 0);

        attn_flash<<<dim3(4, HH, BB), 256, ATTN_DSMEM>>>(qkv, attn);

        gemm_mma<<<dim3(DD/128, MTOK/128), 256, GEMM_SMEM>>>(
            attn, wl + OFF_P, bp, tmp, DD, DD, 0);

        add_ln_kernel<<<MTOK, 256>>>(h, tmp, gA, bA, h);

        gemm_mma<<<dim3(DF/128, MTOK/128), 256, GEMM_SMEM>>>(
            h, wl + OFF_F, bf, mid, DF, DD, 1);

        gemm_mma<<<dim3(DD/128, MTOK/128), 256, GEMM_SMEM>>>(
            mid, wl + OFF_R, br, tmp, DD, DF, 0);

        float* o = (l == LL - 1) ? out : h;
        add_ln_kernel<<<MTOK, 256>>>(h, tmp, gB, bB, o);
    }
}

// round 10
// speedup vs baseline: 1.1219x; 1.1219x over previous
#include <cuda_runtime.h>
#include <cuda_bf16.h>
#include <cuda_fp16.h>
#include <math.h>
#include <stdint.h>

#define BB 8
#define SS 512
#define DD 768
#define HH 12
#define LL 12
#define DH 64
#define DF 3072
#define VV 40478
#define MTOK (BB*SS)

#define K3_D  (3*DD)
#define K3_F  (3*DF)

#define WQ_ELEMS ((size_t)(3*DD) * K3_D)
#define WP_ELEMS ((size_t)DD * K3_D)
#define WF_ELEMS ((size_t)DF * K3_D)
#define WR_ELEMS ((size_t)DD * K3_F)
#define WL_ELEMS (WQ_ELEMS + WP_ELEMS + WF_ELEMS + WR_ELEMS)
#define OFF_Q 0
#define OFF_P (WQ_ELEMS)
#define OFF_F (WQ_ELEMS + WP_ELEMS)
#define OFF_R (WQ_ELEMS + WP_ELEMS + WF_ELEMS)

__device__ __align__(1024) float g_h[MTOK * DD];
__device__ __align__(1024) float g_qkv[MTOK * 3 * DD];
__device__ __align__(1024) float g_attn[MTOK * DD];
__device__ __align__(1024) float g_tmp[MTOK * DD];
__device__ __align__(1024) float g_mid[MTOK * DF];
__device__ __align__(1024) __nv_bfloat16 g_wexp[12 * WL_ELEMS];

__device__ __forceinline__ uint32_t smem_u32(const void* p) {
    uint32_t a;
    asm("{ .reg .u64 t; cvta.to.shared.u64 t, %1; cvt.u32.u64 %0, t; }"
        : "=r"(a) : "l"(p));
    return a;
}
__device__ __forceinline__ void cp16(uint32_t dst, const void* src) {
    asm volatile("cp.async.cg.shared.global [%0], [%1], 16;" :: "r"(dst), "l"(src));
}
__device__ __forceinline__ void cp_commit() {
    asm volatile("cp.async.commit_group;" ::);
}
template<int N>
__device__ __forceinline__ void cp_wait() {
    asm volatile("cp.async.wait_group %0;" :: "n"(N));
}
__device__ __forceinline__ void mma16816(float* c, const uint32_t* a, const uint32_t* b) {
    asm volatile(
        "mma.sync.aligned.m16n8k16.row.col.f32.bf16.bf16.f32 "
        "{%0,%1,%2,%3}, {%4,%5,%6,%7}, {%8,%9}, {%0,%1,%2,%3};"
        : "+f"(c[0]), "+f"(c[1]), "+f"(c[2]), "+f"(c[3])
        : "r"(a[0]), "r"(a[1]), "r"(a[2]), "r"(a[3]), "r"(b[0]), "r"(b[1]));
}
__device__ __forceinline__ void mma_f16(float* c, const uint32_t* a, const uint32_t* b) {
    asm volatile(
        "mma.sync.aligned.m16n8k16.row.col.f32.f16.f16.f32 "
        "{%0,%1,%2,%3}, {%4,%5,%6,%7}, {%8,%9}, {%0,%1,%2,%3};"
        : "+f"(c[0]), "+f"(c[1]), "+f"(c[2]), "+f"(c[3])
        : "r"(a[0]), "r"(a[1]), "r"(a[2]), "r"(a[3]), "r"(b[0]), "r"(b[1]));
}
__device__ __forceinline__ void ldm_x4(uint32_t* r, uint32_t addr) {
    asm volatile("ldmatrix.sync.aligned.m8n8.x4.shared.b16 {%0,%1,%2,%3}, [%4];"
                 : "=r"(r[0]), "=r"(r[1]), "=r"(r[2]), "=r"(r[3]) : "r"(addr));
}
__device__ __forceinline__ uint32_t pkh(float a, float b) {
    __half2 h = __floats2half2_rn(a, b);
    return *reinterpret_cast<uint32_t*>(&h);
}
__device__ __forceinline__ float gelu_f(float x) {
    const float c = 0.7978845608028654f;
    float x3 = x * x * x;
    return 0.5f * x * (1.0f + tanhf(c * (x + 0.044715f * x3)));
}

__global__ void embed_kernel(const int* __restrict__ tokens,
                             const float* __restrict__ we,
                             float* __restrict__ h)
{
    int t = blockIdx.x;
    int s = t % SS;
    int tok = tokens[t];
    const float* wrow = we + (size_t)tok * DD;
    const float* prow = we + (size_t)(VV + s) * DD;
    float* hrow = h + (size_t)t * DD;
    for (int i = threadIdx.x; i < DD; i += blockDim.x)
        hrow[i] = wrow[i] + prow[i];
}

// W[K,N] -> We[N,3K] = [hi|hi|lo]
__global__ __launch_bounds__(256)
void wexpand(const float* __restrict__ W, __nv_bfloat16* __restrict__ We,
             int K, int N)
{
    __shared__ float t[32][33];
    const int n0 = blockIdx.x * 32;
    const int k0 = blockIdx.y * 32;
    const int tx = threadIdx.x & 31;
    const int ty = threadIdx.x >> 5;
    for (int r = ty; r < 32; r += 8)
        t[r][tx] = W[(size_t)(k0 + r) * N + n0 + tx];
    __syncthreads();
    for (int r = ty; r < 32; r += 8) {
        int n = n0 + r, k = k0 + tx;
        float v = t[tx][r];
        __nv_bfloat16 hi = __float2bfloat16(v);
        float lo = v - __bfloat162float(hi);
        size_t ro = (size_t)n * (3 * K);
        We[ro + k]         = hi;
        We[ro + K + k]     = hi;
        We[ro + 2 * K + k] = __float2bfloat16(lo);
    }
}

// C[M,N] = X[M,K](fp32, split on the fly) @ B[N,3K]^T + bias  (proven R6 core)
#define MSTAGES 4
#define APAD 40
#define ASTG (128 * APAD)
#define STG_ELEMS (2 * ASTG)
#define GEMM_SMEM (MSTAGES * STG_ELEMS * 2)

__global__ __launch_bounds__(256, 2)
void gemm_mma(const float* __restrict__ A, const __nv_bfloat16* __restrict__ B,
              const float* __restrict__ bias, float* __restrict__ C,
              int N, int K, int act)
{
    extern __shared__ __nv_bfloat16 sh[];
    const int tid  = threadIdx.x;
    const int wid  = tid >> 5;
    const int lane = tid & 31;
    const int m0 = blockIdx.y * 128;
    const int n0 = blockIdx.x * 128;
    const int wm = (wid & 3) * 32;
    const int wn = (wid >> 2) * 64;
    const int K3 = 3 * K;
    const int nk = K3 >> 5;

    const float* Af = A + (size_t)m0 * K;
    const __nv_bfloat16* Bb = B + (size_t)n0 * K3;

    const int id0 = tid * 2, id1 = tid * 2 + 1;
    const int rb0 = id0 >> 2, cb0 = (id0 & 3) * 8;
    const int rb1 = id1 >> 2, cb1 = (id1 & 3) * 8;

    auto issueB = [&](int kc) {
        __nv_bfloat16* Sb = sh + (kc & 3) * STG_ELEMS + ASTG;
        const __nv_bfloat16* gb = Bb + (size_t)kc * 32;
        cp16(smem_u32(Sb + rb0 * APAD + cb0), gb + (size_t)rb0 * K3 + cb0);
        cp16(smem_u32(Sb + rb1 * APAD + cb1), gb + (size_t)rb1 * K3 + cb1);
        cp_commit();
    };

    int rA[4], cA[4];
    #pragma unroll
    for (int i = 0; i < 4; i++) {
        int idx = tid + i * 256;
        rA[i] = idx >> 3; cA[i] = (idx & 7) * 4;
    }
    float4 pa[4];
    auto ldA = [&](int kc) {
        const int col0 = (kc * 32) % K;
        #pragma unroll
        for (int i = 0; i < 4; i++)
            pa[i] = *(const float4*)(Af + (size_t)rA[i] * K + col0 + cA[i]);
    };
    auto stsA = [&](int kc) {
        const int seg = (kc * 32) / K;
        __nv_bfloat16* Sa = sh + (kc & 3) * STG_ELEMS;
        #pragma unroll
        for (int i = 0; i < 4; i++) {
            float4 v = pa[i];
            if (seg == 1) {
                v.x -= __bfloat162float(__float2bfloat16(v.x));
                v.y -= __bfloat162float(__float2bfloat16(v.y));
                v.z -= __bfloat162float(__float2bfloat16(v.z));
                v.w -= __bfloat162float(__float2bfloat16(v.w));
            }
            __nv_bfloat162 h0 = __floats2bfloat162_rn(v.x, v.y);
            __nv_bfloat162 h1 = __floats2bfloat162_rn(v.z, v.w);
            uint2 w;
            w.x = *reinterpret_cast<uint32_t*>(&h0);
            w.y = *reinterpret_cast<uint32_t*>(&h1);
            *reinterpret_cast<uint2*>(Sa + rA[i] * APAD + cA[i]) = w;
        }
    };

    float acc[2][8][4];
    #pragma unroll
    for (int mt = 0; mt < 2; mt++)
        #pragma unroll
        for (int nt = 0; nt < 8; nt++)
            #pragma unroll
            for (int i = 0; i < 4; i++) acc[mt][nt][i] = 0.0f;

    issueB(0); issueB(1); issueB(2);
    ldA(0); stsA(0);
    ldA(1);
    cp_wait<2>();
    __syncthreads();

    for (int kc = 0; kc < nk; kc++) {
        if (kc + 1 < nk) stsA(kc + 1);
        if (kc + 2 < nk) ldA(kc + 2);
        if (kc + 3 < nk) issueB(kc + 3);

        const __nv_bfloat16* Sa = sh + (kc & 3) * STG_ELEMS;
        const __nv_bfloat16* Sb = Sa + ASTG;
        #pragma unroll
        for (int ks = 0; ks < 2; ks++) {
            const int kb = ks * 16;
            uint32_t af[2][4], bfr[8][2];
            #pragma unroll
            for (int mt = 0; mt < 2; mt++) {
                int row = wm + mt * 16 + (lane & 7) + ((lane >> 3) & 1) * 8;
                int col = kb + (lane >> 4) * 8;
                ldm_x4(af[mt], smem_u32(Sa + row * APAD + col));
            }
            #pragma unroll
            for (int np = 0; np < 4; np++) {
                int nt0 = np * 2;
                int row = wn + (nt0 + (lane >> 4)) * 8 + (lane & 7);
                int col = kb + ((lane >> 3) & 1) * 8;
                uint32_t r4[4];
                ldm_x4(r4, smem_u32(Sb + row * APAD + col));
                bfr[nt0][0] = r4[0]; bfr[nt0][1] = r4[1];
                bfr[nt0 + 1][0] = r4[2]; bfr[nt0 + 1][1] = r4[3];
            }
            #pragma unroll
            for (int mt = 0; mt < 2; mt++)
                #pragma unroll
                for (int nt = 0; nt < 8; nt++)
                    mma16816(acc[mt][nt], af[mt], bfr[nt]);
        }
        if (kc + 1 < nk) { cp_wait<2>(); __syncthreads(); }
    }

    #pragma unroll
    for (int mt = 0; mt < 2; mt++) {
        const int r = m0 + wm + mt * 16 + (lane >> 2);
        #pragma unroll
        for (int nt = 0; nt < 8; nt++) {
            const int c = n0 + wn + nt * 8 + (lane & 3) * 2;
            const float b0 = bias[c], b1 = bias[c + 1];
            float v0 = acc[mt][nt][0] + b0;
            float v1 = acc[mt][nt][1] + b1;
            float v2 = acc[mt][nt][2] + b0;
            float v3 = acc[mt][nt][3] + b1;
            if (act) { v0 = gelu_f(v0); v1 = gelu_f(v1); v2 = gelu_f(v2); v3 = gelu_f(v3); }
            *(float2*)(C + (size_t)r * N + c)       = make_float2(v0, v1);
            *(float2*)(C + (size_t)(r + 8) * N + c) = make_float2(v2, v3);
        }
    }
}

// ---------------- fp16 tensor-core flash attention -------------------------
// Block = (qt, h, b): 128 q rows, 8 warps x 16 rows, K/V tiles of 64.
#define QSTR 72

__global__ __launch_bounds__(256)
void attn_mma(const float* __restrict__ qkv, float* __restrict__ out)
{
    __shared__ __half Qs[128 * QSTR];
    __shared__ __half Ks[64 * QSTR];
    __shared__ __half Vt[64 * QSTR];

    const int tid = threadIdx.x;
    const int wid = tid >> 5;
    const int lane = tid & 31;
    const int qt = blockIdx.x;
    const int h  = blockIdx.y;
    const int b  = blockIdx.z;
    const int wq0 = wid * 16;
    const float* base = qkv + (size_t)b * SS * (3 * DD);

    #pragma unroll
    for (int t = 0; t < 8; t++) {
        int li = tid + t * 256;               // 0..2047
        int row = li >> 4, d4 = (li & 15) * 4;
        float4 v = *(const float4*)(base + (size_t)(qt * 128 + row) * (3 * DD) + h * 64 + d4);
        uint2 w;
        w.x = pkh(v.x * 0.125f, v.y * 0.125f);
        w.y = pkh(v.z * 0.125f, v.w * 0.125f);
        *reinterpret_cast<uint2*>(Qs + row * QSTR + d4) = w;
    }

    float m0 = -1e30f, m1 = -1e30f, l0 = 0.0f, l1 = 0.0f;
    float oacc[8][4];
    #pragma unroll
    for (int nf = 0; nf < 8; nf++)
        #pragma unroll
        for (int j = 0; j < 4; j++) oacc[nf][j] = 0.0f;

    const int nkt = 2 * (qt + 1);
    for (int kt = 0; kt < nkt; kt++) {
        __syncthreads();
        #pragma unroll
        for (int t = 0; t < 4; t++) {
            int li = tid + t * 256;           // 0..1023
            int tok = li >> 4, d4 = (li & 15) * 4;
            const float* kp = base + (size_t)(kt * 64 + tok) * (3 * DD) + DD + h * 64 + d4;
            float4 kv = *(const float4*)kp;
            uint2 w;
            w.x = pkh(kv.x, kv.y);
            w.y = pkh(kv.z, kv.w);
            *reinterpret_cast<uint2*>(Ks + tok * QSTR + d4) = w;
            float4 vv = *(const float4*)(kp + DD);
            Vt[(d4 + 0) * QSTR + tok] = __float2half(vv.x);
            Vt[(d4 + 1) * QSTR + tok] = __float2half(vv.y);
            Vt[(d4 + 2) * QSTR + tok] = __float2half(vv.z);
            Vt[(d4 + 3) * QSTR + tok] = __float2half(vv.w);
        }
        __syncthreads();

        // S = Q K^T
        float sacc[8][4];
        #pragma unroll
        for (int nf = 0; nf < 8; nf++)
            #pragma unroll
            for (int j = 0; j < 4; j++) sacc[nf][j] = 0.0f;

        const int arow = wq0 + (lane & 15);
        const int brow = (lane >> 4) * 8 + (lane & 7);
        #pragma unroll
        for (int kf = 0; kf < 4; kf++) {
            uint32_t aq[4];
            ldm_x4(aq, smem_u32(Qs + arow * QSTR + kf * 16 + (lane >> 4) * 8));
            const int bcol = kf * 16 + ((lane >> 3) & 1) * 8;
            #pragma unroll
            for (int g = 0; g < 4; g++) {
                uint32_t r4[4];
                ldm_x4(r4, smem_u32(Ks + (g * 16 + brow) * QSTR + bcol));
                uint32_t b0[2] = {r4[0], r4[1]}, b1[2] = {r4[2], r4[3]};
                mma_f16(sacc[2 * g],     aq, b0);
                mma_f16(sacc[2 * g + 1], aq, b1);
            }
        }

        // causal mask (diagonal tiles only)
        if (kt >= 2 * qt) {
            const int r0g = qt * 128 + wq0 + (lane >> 2);
            const int r1g = r0g + 8;
            #pragma unroll
            for (int nf = 0; nf < 8; nf++) {
                int cg = kt * 64 + nf * 8 + (lane & 3) * 2;
                if (cg     > r0g) sacc[nf][0] = -1e9f;
                if (cg + 1 > r0g) sacc[nf][1] = -1e9f;
                if (cg     > r1g) sacc[nf][2] = -1e9f;
                if (cg + 1 > r1g) sacc[nf][3] = -1e9f;
            }
        }

        // online softmax in registers
        float mx0 = -1e30f, mx1 = -1e30f;
        #pragma unroll
        for (int nf = 0; nf < 8; nf++) {
            mx0 = fmaxf(mx0, fmaxf(sacc[nf][0], sacc[nf][1]));
            mx1 = fmaxf(mx1, fmaxf(sacc[nf][2], sacc[nf][3]));
        }
        mx0 = fmaxf(mx0, __shfl_xor_sync(0xffffffffu, mx0, 1));
        mx0 = fmaxf(mx0, __shfl_xor_sync(0xffffffffu, mx0, 2));
        mx1 = fmaxf(mx1, __shfl_xor_sync(0xffffffffu, mx1, 1));
        mx1 = fmaxf(mx1, __shfl_xor_sync(0xffffffffu, mx1, 2));
        float mn0 = fmaxf(m0, mx0), mn1 = fmaxf(m1, mx1);
        float a0 = __expf(m0 - mn0), a1 = __expf(m1 - mn1);
        m0 = mn0; m1 = mn1;

        float rs0 = 0.0f, rs1 = 0.0f;
        #pragma unroll
        for (int nf = 0; nf < 8; nf++) {
            sacc[nf][0] = __expf(sacc[nf][0] - m0);
            sacc[nf][1] = __expf(sacc[nf][1] - m0);
            sacc[nf][2] = __expf(sacc[nf][2] - m1);
            sacc[nf][3] = __expf(sacc[nf][3] - m1);
            rs0 += sacc[nf][0] + sacc[nf][1];
            rs1 += sacc[nf][2] + sacc[nf][3];
        }
        rs0 += __shfl_xor_sync(0xffffffffu, rs0, 1);
        rs0 += __shfl_xor_sync(0xffffffffu, rs0, 2);
        rs1 += __shfl_xor_sync(0xffffffffu, rs1, 1);
        rs1 += __shfl_xor_sync(0xffffffffu, rs1, 2);
        l0 = l0 * a0 + rs0;
        l1 = l1 * a1 + rs1;
        #pragma unroll
        for (int nf = 0; nf < 8; nf++) {
            oacc[nf][0] *= a0; oacc[nf][1] *= a0;
            oacc[nf][2] *= a1; oacc[nf][3] *= a1;
        }

        // O += P V  (P fragments rebuilt in registers)
        #pragma unroll
        for (int kf = 0; kf < 4; kf++) {
            uint32_t ap[4];
            ap[0] = pkh(sacc[2 * kf][0],     sacc[2 * kf][1]);
            ap[1] = pkh(sacc[2 * kf][2],     sacc[2 * kf][3]);
            ap[2] = pkh(sacc[2 * kf + 1][0], sacc[2 * kf + 1][1]);
            ap[3] = pkh(sacc[2 * kf + 1][2], sacc[2 * kf + 1][3]);
            const int bcol = kf * 16 + ((lane >> 3) & 1) * 8;
            #pragma unroll
            for (int g = 0; g < 4; g++) {
                uint32_t r4[4];
                ldm_x4(r4, smem_u32(Vt + (g * 16 + brow) * QSTR + bcol));
                uint32_t b0[2] = {r4[0], r4[1]}, b1[2] = {r4[2], r4[3]};
                mma_f16(oacc[2 * g],     ap, b0);
                mma_f16(oacc[2 * g + 1], ap, b1);
            }
        }
    }

    const float inv0 = 1.0f / l0, inv1 = 1.0f / l1;
    const int rg = b * SS + qt * 128 + wq0 + (lane >> 2);
    #pragma unroll
    for (int nf = 0; nf < 8; nf++) {
        const int c = h * 64 + nf * 8 + (lane & 3) * 2;
        *(float2*)(out + (size_t)rg * DD + c) =
            make_float2(oacc[nf][0] * inv0, oacc[nf][1] * inv0);
        *(float2*)(out + (size_t)(rg + 8) * DD + c) =
            make_float2(oacc[nf][2] * inv1, oacc[nf][3] * inv1);
    }
}

__global__ __launch_bounds__(256)
void add_ln_kernel(const float* __restrict__ x, const float* __restrict__ a,
                   const float* __restrict__ g, const float* __restrict__ bb,
                   float* __restrict__ out)
{
    const int row = blockIdx.x;
    const int tid = threadIdx.x;
    __shared__ float red[256];

    const size_t off = (size_t)row * DD;
    float v[3];
    float s = 0.0f;
    #pragma unroll
    for (int i = 0; i < 3; i++) {
        int c = tid + 256 * i;
        v[i] = x[off + c] + a[off + c];
        s += v[i];
    }
    red[tid] = s; __syncthreads();
    for (int st = 128; st > 0; st >>= 1) {
        if (tid < st) red[tid] += red[tid + st];
        __syncthreads();
    }
    const float mean = red[0] * (1.0f / DD);
    __syncthreads();

    float s2 = 0.0f;
    #pragma unroll
    for (int i = 0; i < 3; i++) {
        float d = v[i] - mean;
        s2 += d * d;
    }
    red[tid] = s2; __syncthreads();
    for (int st = 128; st > 0; st >>= 1) {
        if (tid < st) red[tid] += red[tid + st];
        __syncthreads();
    }
    const float inv = rsqrtf(red[0] * (1.0f / DD) + 1e-5f);

    #pragma unroll
    for (int i = 0; i < 3; i++) {
        int c = tid + 256 * i;
        out[off + c] = g[c] * (v[i] - mean) * inv + bb[c];
    }
}

extern "C" void kernel_launch(void* const* d_in, const int* in_sizes, int n_in,
                              void* d_out, int out_size)
{
    const int*   tokens = (const int*)  d_in[0];
    const float* we     = (const float*)d_in[1];
    const float* wqkv   = (const float*)d_in[2];
    const float* bqkv   = (const float*)d_in[3];
    const float* wproj  = (const float*)d_in[4];
    const float* bproj  = (const float*)d_in[5];
    const float* g1     = (const float*)d_in[6];
    const float* b1     = (const float*)d_in[7];
    const float* wfc    = (const float*)d_in[8];
    const float* bfc    = (const float*)d_in[9];
    const float* wpr    = (const float*)d_in[10];
    const float* bpr    = (const float*)d_in[11];
    const float* g2     = (const float*)d_in[12];
    const float* b2     = (const float*)d_in[13];
    float* out = (float*)d_out;

    float *h, *qkv, *attn, *tmp, *mid;
    __nv_bfloat16 *wex;
    cudaGetSymbolAddress((void**)&h,    g_h);
    cudaGetSymbolAddress((void**)&qkv,  g_qkv);
    cudaGetSymbolAddress((void**)&attn, g_attn);
    cudaGetSymbolAddress((void**)&tmp,  g_tmp);
    cudaGetSymbolAddress((void**)&mid,  g_mid);
    cudaGetSymbolAddress((void**)&wex,  g_wexp);

    cudaFuncSetAttribute(gemm_mma, cudaFuncAttributeMaxDynamicSharedMemorySize, GEMM_SMEM);

    for (int l = 0; l < LL; l++) {
        __nv_bfloat16* wl = wex + (size_t)l * WL_ELEMS;
        wexpand<<<dim3(3*DD/32, DD/32), 256>>>(wqkv  + (size_t)l*DD*3*DD, wl + OFF_Q, DD, 3*DD);
        wexpand<<<dim3(DD/32,   DD/32), 256>>>(wproj + (size_t)l*DD*DD,   wl + OFF_P, DD, DD);
        wexpand<<<dim3(DF/32,   DD/32), 256>>>(wfc   + (size_t)l*DD*DF,   wl + OFF_F, DD, DF);
        wexpand<<<dim3(DD/32,   DF/32), 256>>>(wpr   + (size_t)l*DF*DD,   wl + OFF_R, DF, DD);
    }

    embed_kernel<<<MTOK, 256>>>(tokens, we, h);

    for (int l = 0; l < LL; l++) {
        const __nv_bfloat16* wl = wex + (size_t)l * WL_ELEMS;
        const float* bq = bqkv  + (size_t)l * 3 * DD;
        const float* bp = bproj + (size_t)l * DD;
        const float* gA = g1 + (size_t)l * DD;
        const float* bA = b1 + (size_t)l * DD;
        const float* bf = bfc + (size_t)l * DF;
        const float* br = bpr + (size_t)l * DD;
        const float* gB = g2 + (size_t)l * DD;
        const float* bB = b2 + (size_t)l * DD;

        gemm_mma<<<dim3(3*DD/128, MTOK/128), 256, GEMM_SMEM>>>(
            h, wl + OFF_Q, bq, qkv, 3*DD, DD, 0);

        attn_mma<<<dim3(4, HH, BB), 256>>>(qkv, attn);

        gemm_mma<<<dim3(DD/128, MTOK/128), 256, GEMM_SMEM>>>(
            attn, wl + OFF_P, bp, tmp, DD, DD, 0);

        add_ln_kernel<<<MTOK, 256>>>(h, tmp, gA, bA, h);

        gemm_mma<<<dim3(DF/128, MTOK/128), 256, GEMM_SMEM>>>(
            h, wl + OFF_F, bf, mid, DF, DD, 1);

        gemm_mma<<<dim3(DD/128, MTOK/128), 256, GEMM_SMEM>>>(
            mid, wl + OFF_R, br, tmp, DD, DF, 0);

        float* o = (l == LL - 1) ? out : h;
        add_ln_kernel<<<MTOK, 256>>>(h, tmp, gB, bB, o);
    }
}

// round 13
// speedup vs baseline: 1.5832x; 1.4112x over previous
#include <cuda_runtime.h>
#include <cuda_bf16.h>
#include <cuda_fp16.h>
#include <math.h>
#include <stdint.h>

#define BB 8
#define SS 512
#define DD 768
#define HH 12
#define LL 12
#define DH 64
#define DF 3072
#define VV 40478
#define MTOK (BB*SS)

// 2-term split-fp16 weights: [hi | lo] along K
#define K2_D  (2*DD)       // 1536
#define K2_F  (2*DF)       // 6144

#define WQ_ELEMS ((size_t)(3*DD) * K2_D)
#define WP_ELEMS ((size_t)DD * K2_D)
#define WF_ELEMS ((size_t)DF * K2_D)
#define WR_ELEMS ((size_t)DD * K2_F)
#define WL_ELEMS (WQ_ELEMS + WP_ELEMS + WF_ELEMS + WR_ELEMS)
#define OFF_Q 0
#define OFF_P (WQ_ELEMS)
#define OFF_F (WQ_ELEMS + WP_ELEMS)
#define OFF_R (WQ_ELEMS + WP_ELEMS + WF_ELEMS)

__device__ __align__(1024) float g_h[MTOK * DD];
__device__ __align__(1024) float g_qkv[MTOK * 3 * DD];
__device__ __align__(1024) float g_attn[MTOK * DD];
__device__ __align__(1024) float g_tmp[MTOK * DD];
__device__ __align__(1024) float g_mid[MTOK * DF];
__device__ __align__(1024) __half g_wexp[12 * WL_ELEMS];

__device__ __forceinline__ uint32_t smem_u32(const void* p) {
    uint32_t a;
    asm("{ .reg .u64 t; cvta.to.shared.u64 t, %1; cvt.u32.u64 %0, t; }"
        : "=r"(a) : "l"(p));
    return a;
}
__device__ __forceinline__ void cp16(uint32_t dst, const void* src) {
    asm volatile("cp.async.cg.shared.global [%0], [%1], 16;" :: "r"(dst), "l"(src));
}
__device__ __forceinline__ void cp_commit() {
    asm volatile("cp.async.commit_group;" ::);
}
template<int N>
__device__ __forceinline__ void cp_wait() {
    asm volatile("cp.async.wait_group %0;" :: "n"(N));
}
__device__ __forceinline__ void mma_f16(float* c, const uint32_t* a, const uint32_t* b) {
    asm volatile(
        "mma.sync.aligned.m16n8k16.row.col.f32.f16.f16.f32 "
        "{%0,%1,%2,%3}, {%4,%5,%6,%7}, {%8,%9}, {%0,%1,%2,%3};"
        : "+f"(c[0]), "+f"(c[1]), "+f"(c[2]), "+f"(c[3])
        : "r"(a[0]), "r"(a[1]), "r"(a[2]), "r"(a[3]), "r"(b[0]), "r"(b[1]));
}
__device__ __forceinline__ void ldm_x4(uint32_t* r, uint32_t addr) {
    asm volatile("ldmatrix.sync.aligned.m8n8.x4.shared.b16 {%0,%1,%2,%3}, [%4];"
                 : "=r"(r[0]), "=r"(r[1]), "=r"(r[2]), "=r"(r[3]) : "r"(addr));
}
__device__ __forceinline__ uint32_t pkh(float a, float b) {
    __half2 h = __floats2half2_rn(a, b);
    return *reinterpret_cast<uint32_t*>(&h);
}
__device__ __forceinline__ float gelu_f(float x) {
    const float c = 0.7978845608028654f;
    float x3 = x * x * x;
    return 0.5f * x * (1.0f + tanhf(c * (x + 0.044715f * x3)));
}

__global__ void embed_kernel(const int* __restrict__ tokens,
                             const float* __restrict__ we,
                             float* __restrict__ h)
{
    int t = blockIdx.x;
    int s = t % SS;
    int tok = tokens[t];
    const float* wrow = we + (size_t)tok * DD;
    const float* prow = we + (size_t)(VV + s) * DD;
    float* hrow = h + (size_t)t * DD;
    for (int i = threadIdx.x; i < DD; i += blockDim.x)
        hrow[i] = wrow[i] + prow[i];
}

// W[K,N] -> We[N,2K] = [hi | lo]  (fp16)
__global__ __launch_bounds__(256)
void wexpand(const float* __restrict__ W, __half* __restrict__ We,
             int K, int N)
{
    __shared__ float t[32][33];
    const int n0 = blockIdx.x * 32;
    const int k0 = blockIdx.y * 32;
    const int tx = threadIdx.x & 31;
    const int ty = threadIdx.x >> 5;
    for (int r = ty; r < 32; r += 8)
        t[r][tx] = W[(size_t)(k0 + r) * N + n0 + tx];
    __syncthreads();
    for (int r = ty; r < 32; r += 8) {
        int n = n0 + r, k = k0 + tx;
        float v = t[tx][r];
        __half hi = __float2half(v);
        float lo = v - __half2float(hi);
        size_t ro = (size_t)n * (2 * K);
        We[ro + k]     = hi;
        We[ro + K + k] = __float2half(lo);
    }
}

// C[M,N] = X[M,K](fp32, split-fp16 on the fly) @ B[N,2K]^T + bias
#define MSTAGES 4
#define APAD 40
#define ASTG (128 * APAD)
#define STG_ELEMS (2 * ASTG)
#define GEMM_SMEM (MSTAGES * STG_ELEMS * 2)

__global__ __launch_bounds__(256, 2)
void gemm_mma(const float* __restrict__ A, const __half* __restrict__ B,
              const float* __restrict__ bias, float* __restrict__ C,
              int N, int K, int act)
{
    extern __shared__ __half sh[];
    const int tid  = threadIdx.x;
    const int wid  = tid >> 5;
    const int lane = tid & 31;
    const int m0 = blockIdx.y * 128;
    const int n0 = blockIdx.x * 128;
    const int wm = (wid & 3) * 32;
    const int wn = (wid >> 2) * 64;
    const int K2 = 2 * K;
    const int nk = K2 >> 5;

    const float* Af = A + (size_t)m0 * K;
    const __half* Bb = B + (size_t)n0 * K2;

    const int id0 = tid * 2, id1 = tid * 2 + 1;
    const int rb0 = id0 >> 2, cb0 = (id0 & 3) * 8;
    const int rb1 = id1 >> 2, cb1 = (id1 & 3) * 8;

    auto issueB = [&](int kc) {
        __half* Sb = sh + (kc & 3) * STG_ELEMS + ASTG;
        const __half* gb = Bb + (size_t)kc * 32;
        cp16(smem_u32(Sb + rb0 * APAD + cb0), gb + (size_t)rb0 * K2 + cb0);
        cp16(smem_u32(Sb + rb1 * APAD + cb1), gb + (size_t)rb1 * K2 + cb1);
        cp_commit();
    };

    int rA[4], cA[4];
    #pragma unroll
    for (int i = 0; i < 4; i++) {
        int idx = tid + i * 256;
        rA[i] = idx >> 3; cA[i] = (idx & 7) * 4;
    }
    float4 pa[4];
    auto ldA = [&](int kc) {
        const int col0 = (kc * 32) % K;
        #pragma unroll
        for (int i = 0; i < 4; i++)
            pa[i] = *(const float4*)(Af + (size_t)rA[i] * K + col0 + cA[i]);
    };
    auto stsA = [&](int kc) {
        const int seg = (kc * 32) / K;   // 0: hi, 1: lo
        __half* Sa = sh + (kc & 3) * STG_ELEMS;
        #pragma unroll
        for (int i = 0; i < 4; i++) {
            float4 v = pa[i];
            if (seg == 1) {
                v.x -= __half2float(__float2half(v.x));
                v.y -= __half2float(__float2half(v.y));
                v.z -= __half2float(__float2half(v.z));
                v.w -= __half2float(__float2half(v.w));
            }
            uint2 w;
            w.x = pkh(v.x, v.y);
            w.y = pkh(v.z, v.w);
            *reinterpret_cast<uint2*>(Sa + rA[i] * APAD + cA[i]) = w;
        }
    };

    float acc[2][8][4];
    #pragma unroll
    for (int mt = 0; mt < 2; mt++)
        #pragma unroll
        for (int nt = 0; nt < 8; nt++)
            #pragma unroll
            for (int i = 0; i < 4; i++) acc[mt][nt][i] = 0.0f;

    issueB(0); issueB(1); issueB(2);
    ldA(0); stsA(0);
    ldA(1);
    cp_wait<2>();
    __syncthreads();

    for (int kc = 0; kc < nk; kc++) {
        if (kc + 1 < nk) stsA(kc + 1);
        if (kc + 2 < nk) ldA(kc + 2);
        if (kc + 3 < nk) issueB(kc + 3);

        const __half* Sa = sh + (kc & 3) * STG_ELEMS;
        const __half* Sb = Sa + ASTG;
        #pragma unroll
        for (int ks = 0; ks < 2; ks++) {
            const int kb = ks * 16;
            uint32_t af[2][4], bfr[8][2];
            #pragma unroll
            for (int mt = 0; mt < 2; mt++) {
                int row = wm + mt * 16 + (lane & 7) + ((lane >> 3) & 1) * 8;
                int col = kb + (lane >> 4) * 8;
                ldm_x4(af[mt], smem_u32(Sa + row * APAD + col));
            }
            #pragma unroll
            for (int np = 0; np < 4; np++) {
                int nt0 = np * 2;
                int row = wn + (nt0 + (lane >> 4)) * 8 + (lane & 7);
                int col = kb + ((lane >> 3) & 1) * 8;
                uint32_t r4[4];
                ldm_x4(r4, smem_u32(Sb + row * APAD + col));
                bfr[nt0][0] = r4[0]; bfr[nt0][1] = r4[1];
                bfr[nt0 + 1][0] = r4[2]; bfr[nt0 + 1][1] = r4[3];
            }
            #pragma unroll
            for (int mt = 0; mt < 2; mt++)
                #pragma unroll
                for (int nt = 0; nt < 8; nt++)
                    mma_f16(acc[mt][nt], af[mt], bfr[nt]);
        }
        if (kc + 1 < nk) { cp_wait<2>(); __syncthreads(); }
    }

    #pragma unroll
    for (int mt = 0; mt < 2; mt++) {
        const int r = m0 + wm + mt * 16 + (lane >> 2);
        #pragma unroll
        for (int nt = 0; nt < 8; nt++) {
            const int c = n0 + wn + nt * 8 + (lane & 3) * 2;
            const float b0 = bias[c], b1 = bias[c + 1];
            float v0 = acc[mt][nt][0] + b0;
            float v1 = acc[mt][nt][1] + b1;
            float v2 = acc[mt][nt][2] + b0;
            float v3 = acc[mt][nt][3] + b1;
            if (act) { v0 = gelu_f(v0); v1 = gelu_f(v1); v2 = gelu_f(v2); v3 = gelu_f(v3); }
            *(float2*)(C + (size_t)r * N + c)       = make_float2(v0, v1);
            *(float2*)(C + (size_t)(r + 8) * N + c) = make_float2(v2, v3);
        }
    }
}

// ---------------- fp16 tensor-core flash attention (proven R8 core) --------
#define QSTR 72

__global__ __launch_bounds__(256)
void attn_mma(const float* __restrict__ qkv, float* __restrict__ out)
{
    __shared__ __half Qs[128 * QSTR];
    __shared__ __half Ks[64 * QSTR];
    __shared__ __half Vt[64 * QSTR];

    const int tid = threadIdx.x;
    const int wid = tid >> 5;
    const int lane = tid & 31;
    const int qt = blockIdx.x;
    const int h  = blockIdx.y;
    const int b  = blockIdx.z;
    const int wq0 = wid * 16;
    const float* base = qkv + (size_t)b * SS * (3 * DD);

    #pragma unroll
    for (int t = 0; t < 8; t++) {
        int li = tid + t * 256;
        int row = li >> 4, d4 = (li & 15) * 4;
        float4 v = *(const float4*)(base + (size_t)(qt * 128 + row) * (3 * DD) + h * 64 + d4);
        uint2 w;
        w.x = pkh(v.x * 0.125f, v.y * 0.125f);
        w.y = pkh(v.z * 0.125f, v.w * 0.125f);
        *reinterpret_cast<uint2*>(Qs + row * QSTR + d4) = w;
    }

    float m0 = -1e30f, m1 = -1e30f, l0 = 0.0f, l1 = 0.0f;
    float oacc[8][4];
    #pragma unroll
    for (int nf = 0; nf < 8; nf++)
        #pragma unroll
        for (int j = 0; j < 4; j++) oacc[nf][j] = 0.0f;

    const int nkt = 2 * (qt + 1);
    for (int kt = 0; kt < nkt; kt++) {
        __syncthreads();
        #pragma unroll
        for (int t = 0; t < 4; t++) {
            int li = tid + t * 256;
            int tok = li >> 4, d4 = (li & 15) * 4;
            const float* kp = base + (size_t)(kt * 64 + tok) * (3 * DD) + DD + h * 64 + d4;
            float4 kv = *(const float4*)kp;
            uint2 w;
            w.x = pkh(kv.x, kv.y);
            w.y = pkh(kv.z, kv.w);
            *reinterpret_cast<uint2*>(Ks + tok * QSTR + d4) = w;
            float4 vv = *(const float4*)(kp + DD);
            Vt[(d4 + 0) * QSTR + tok] = __float2half(vv.x);
            Vt[(d4 + 1) * QSTR + tok] = __float2half(vv.y);
            Vt[(d4 + 2) * QSTR + tok] = __float2half(vv.z);
            Vt[(d4 + 3) * QSTR + tok] = __float2half(vv.w);
        }
        __syncthreads();

        float sacc[8][4];
        #pragma unroll
        for (int nf = 0; nf < 8; nf++)
            #pragma unroll
            for (int j = 0; j < 4; j++) sacc[nf][j] = 0.0f;

        const int arow = wq0 + (lane & 15);
        const int brow = (lane >> 4) * 8 + (lane & 7);
        #pragma unroll
        for (int kf = 0; kf < 4; kf++) {
            uint32_t aq[4];
            ldm_x4(aq, smem_u32(Qs + arow * QSTR + kf * 16 + (lane >> 4) * 8));
            const int bcol = kf * 16 + ((lane >> 3) & 1) * 8;
            #pragma unroll
            for (int g = 0; g < 4; g++) {
                uint32_t r4[4];
                ldm_x4(r4, smem_u32(Ks + (g * 16 + brow) * QSTR + bcol));
                uint32_t b0[2] = {r4[0], r4[1]}, b1[2] = {r4[2], r4[3]};
                mma_f16(sacc[2 * g],     aq, b0);
                mma_f16(sacc[2 * g + 1], aq, b1);
            }
        }

        if (kt >= 2 * qt) {
            const int r0g = qt * 128 + wq0 + (lane >> 2);
            const int r1g = r0g + 8;
            #pragma unroll
            for (int nf = 0; nf < 8; nf++) {
                int cg = kt * 64 + nf * 8 + (lane & 3) * 2;
                if (cg     > r0g) sacc[nf][0] = -1e9f;
                if (cg + 1 > r0g) sacc[nf][1] = -1e9f;
                if (cg     > r1g) sacc[nf][2] = -1e9f;
                if (cg + 1 > r1g) sacc[nf][3] = -1e9f;
            }
        }

        float mx0 = -1e30f, mx1 = -1e30f;
        #pragma unroll
        for (int nf = 0; nf < 8; nf++) {
            mx0 = fmaxf(mx0, fmaxf(sacc[nf][0], sacc[nf][1]));
            mx1 = fmaxf(mx1, fmaxf(sacc[nf][2], sacc[nf][3]));
        }
        mx0 = fmaxf(mx0, __shfl_xor_sync(0xffffffffu, mx0, 1));
        mx0 = fmaxf(mx0, __shfl_xor_sync(0xffffffffu, mx0, 2));
        mx1 = fmaxf(mx1, __shfl_xor_sync(0xffffffffu, mx1, 1));
        mx1 = fmaxf(mx1, __shfl_xor_sync(0xffffffffu, mx1, 2));
        float mn0 = fmaxf(m0, mx0), mn1 = fmaxf(m1, mx1);
        float a0 = __expf(m0 - mn0), a1 = __expf(m1 - mn1);
        m0 = mn0; m1 = mn1;

        float rs0 = 0.0f, rs1 = 0.0f;
        #pragma unroll
        for (int nf = 0; nf < 8; nf++) {
            sacc[nf][0] = __expf(sacc[nf][0] - m0);
            sacc[nf][1] = __expf(sacc[nf][1] - m0);
            sacc[nf][2] = __expf(sacc[nf][2] - m1);
            sacc[nf][3] = __expf(sacc[nf][3] - m1);
            rs0 += sacc[nf][0] + sacc[nf][1];
            rs1 += sacc[nf][2] + sacc[nf][3];
        }
        rs0 += __shfl_xor_sync(0xffffffffu, rs0, 1);
        rs0 += __shfl_xor_sync(0xffffffffu, rs0, 2);
        rs1 += __shfl_xor_sync(0xffffffffu, rs1, 1);
        rs1 += __shfl_xor_sync(0xffffffffu, rs1, 2);
        l0 = l0 * a0 + rs0;
        l1 = l1 * a1 + rs1;
        #pragma unroll
        for (int nf = 0; nf < 8; nf++) {
            oacc[nf][0] *= a0; oacc[nf][1] *= a0;
            oacc[nf][2] *= a1; oacc[nf][3] *= a1;
        }

        #pragma unroll
        for (int kf = 0; kf < 4; kf++) {
            uint32_t ap[4];
            ap[0] = pkh(sacc[2 * kf][0],     sacc[2 * kf][1]);
            ap[1] = pkh(sacc[2 * kf][2],     sacc[2 * kf][3]);
            ap[2] = pkh(sacc[2 * kf + 1][0], sacc[2 * kf + 1][1]);
            ap[3] = pkh(sacc[2 * kf + 1][2], sacc[2 * kf + 1][3]);
            const int bcol = kf * 16 + ((lane >> 3) & 1) * 8;
            #pragma unroll
            for (int g = 0; g < 4; g++) {
                uint32_t r4[4];
                ldm_x4(r4, smem_u32(Vt + (g * 16 + brow) * QSTR + bcol));
                uint32_t b0[2] = {r4[0], r4[1]}, b1[2] = {r4[2], r4[3]};
                mma_f16(oacc[2 * g],     ap, b0);
                mma_f16(oacc[2 * g + 1], ap, b1);
            }
        }
    }

    const float inv0 = 1.0f / l0, inv1 = 1.0f / l1;
    const int rg = b * SS + qt * 128 + wq0 + (lane >> 2);
    #pragma unroll
    for (int nf = 0; nf < 8; nf++) {
        const int c = h * 64 + nf * 8 + (lane & 3) * 2;
        *(float2*)(out + (size_t)rg * DD + c) =
            make_float2(oacc[nf][0] * inv0, oacc[nf][1] * inv0);
        *(float2*)(out + (size_t)(rg + 8) * DD + c) =
            make_float2(oacc[nf][2] * inv1, oacc[nf][3] * inv1);
    }
}

__global__ __launch_bounds__(256)
void add_ln_kernel(const float* __restrict__ x, const float* __restrict__ a,
                   const float* __restrict__ g, const float* __restrict__ bb,
                   float* __restrict__ out)
{
    const int row = blockIdx.x;
    const int tid = threadIdx.x;
    __shared__ float red[256];

    const size_t off = (size_t)row * DD;
    float v[3];
    float s = 0.0f;
    #pragma unroll
    for (int i = 0; i < 3; i++) {
        int c = tid + 256 * i;
        v[i] = x[off + c] + a[off + c];
        s += v[i];
    }
    red[tid] = s; __syncthreads();
    for (int st = 128; st > 0; st >>= 1) {
        if (tid < st) red[tid] += red[tid + st];
        __syncthreads();
    }
    const float mean = red[0] * (1.0f / DD);
    __syncthreads();

    float s2 = 0.0f;
    #pragma unroll
    for (int i = 0; i < 3; i++) {
        float d = v[i] - mean;
        s2 += d * d;
    }
    red[tid] = s2; __syncthreads();
    for (int st = 128; st > 0; st >>= 1) {
        if (tid < st) red[tid] += red[tid + st];
        __syncthreads();
    }
    const float inv = rsqrtf(red[0] * (1.0f / DD) + 1e-5f);

    #pragma unroll
    for (int i = 0; i < 3; i++) {
        int c = tid + 256 * i;
        out[off + c] = g[c] * (v[i] - mean) * inv + bb[c];
    }
}

extern "C" void kernel_launch(void* const* d_in, const int* in_sizes, int n_in,
                              void* d_out, int out_size)
{
    const int*   tokens = (const int*)  d_in[0];
    const float* we     = (const float*)d_in[1];
    const float* wqkv   = (const float*)d_in[2];
    const float* bqkv   = (const float*)d_in[3];
    const float* wproj  = (const float*)d_in[4];
    const float* bproj  = (const float*)d_in[5];
    const float* g1     = (const float*)d_in[6];
    const float* b1     = (const float*)d_in[7];
    const float* wfc    = (const float*)d_in[8];
    const float* bfc    = (const float*)d_in[9];
    const float* wpr    = (const float*)d_in[10];
    const float* bpr    = (const float*)d_in[11];
    const float* g2     = (const float*)d_in[12];
    const float* b2     = (const float*)d_in[13];
    float* out = (float*)d_out;

    float *h, *qkv, *attn, *tmp, *mid;
    __half *wex;
    cudaGetSymbolAddress((void**)&h,    g_h);
    cudaGetSymbolAddress((void**)&qkv,  g_qkv);
    cudaGetSymbolAddress((void**)&attn, g_attn);
    cudaGetSymbolAddress((void**)&tmp,  g_tmp);
    cudaGetSymbolAddress((void**)&mid,  g_mid);
    cudaGetSymbolAddress((void**)&wex,  g_wexp);

    cudaFuncSetAttribute(gemm_mma, cudaFuncAttributeMaxDynamicSharedMemorySize, GEMM_SMEM);

    for (int l = 0; l < LL; l++) {
        __half* wl = wex + (size_t)l * WL_ELEMS;
        wexpand<<<dim3(3*DD/32, DD/32), 256>>>(wqkv  + (size_t)l*DD*3*DD, wl + OFF_Q, DD, 3*DD);
        wexpand<<<dim3(DD/32,   DD/32), 256>>>(wproj + (size_t)l*DD*DD,   wl + OFF_P, DD, DD);
        wexpand<<<dim3(DF/32,   DD/32), 256>>>(wfc   + (size_t)l*DD*DF,   wl + OFF_F, DD, DF);
        wexpand<<<dim3(DD/32,   DF/32), 256>>>(wpr   + (size_t)l*DF*DD,   wl + OFF_R, DF, DD);
    }

    embed_kernel<<<MTOK, 256>>>(tokens, we, h);

    for (int l = 0; l < LL; l++) {
        const __half* wl = wex + (size_t)l * WL_ELEMS;
        const float* bq = bqkv  + (size_t)l * 3 * DD;
        const float* bp = bproj + (size_t)l * DD;
        const float* gA = g1 + (size_t)l * DD;
        const float* bA = b1 + (size_t)l * DD;
        const float* bf = bfc + (size_t)l * DF;
        const float* br = bpr + (size_t)l * DD;
        const float* gB = g2 + (size_t)l * DD;
        const float* bB = b2 + (size_t)l * DD;

        gemm_mma<<<dim3(3*DD/128, MTOK/128), 256, GEMM_SMEM>>>(
            h, wl + OFF_Q, bq, qkv, 3*DD, DD, 0);

        attn_mma<<<dim3(4, HH, BB), 256>>>(qkv, attn);

        gemm_mma<<<dim3(DD/128, MTOK/128), 256, GEMM_SMEM>>>(
            attn, wl + OFF_P, bp, tmp, DD, DD, 0);

        add_ln_kernel<<<MTOK, 256>>>(h, tmp, gA, bA, h);

        gemm_mma<<<dim3(DF/128, MTOK/128), 256, GEMM_SMEM>>>(
            h, wl + OFF_F, bf, mid, DF, DD, 1);

        gemm_mma<<<dim3(DD/128, MTOK/128), 256, GEMM_SMEM>>>(
            mid, wl + OFF_R, br, tmp, DD, DF, 0);

        float* o = (l == LL - 1) ? out : h;
        add_ln_kernel<<<MTOK, 256>>>(h, tmp, gB, bB, o);
    }
}

// round 14
// speedup vs baseline: 2.8192x; 1.7807x over previous
#include <cuda_runtime.h>
#include <cuda_fp16.h>
#include <math.h>
#include <stdint.h>

#define BB 8
#define SS 512
#define DD 768
#define HH 12
#define LL 12
#define DH 64
#define DF 3072
#define VV 40478
#define MTOK (BB*SS)

// plain fp16 weights, transposed: We[N,K]
#define WQ_ELEMS ((size_t)(3*DD) * DD)
#define WP_ELEMS ((size_t)DD * DD)
#define WF_ELEMS ((size_t)DF * DD)
#define WR_ELEMS ((size_t)DD * DF)
#define WL_ELEMS (WQ_ELEMS + WP_ELEMS + WF_ELEMS + WR_ELEMS)
#define OFF_Q 0
#define OFF_P (WQ_ELEMS)
#define OFF_F (WQ_ELEMS + WP_ELEMS)
#define OFF_R (WQ_ELEMS + WP_ELEMS + WF_ELEMS)

__device__ __align__(1024) float g_h[MTOK * DD];
__device__ __align__(1024) float g_qkv[MTOK * 3 * DD];
__device__ __align__(1024) float g_attn[MTOK * DD];
__device__ __align__(1024) float g_tmp[MTOK * DD];
__device__ __align__(1024) float g_mid[MTOK * DF];
__device__ __align__(1024) __half g_wexp[12 * WL_ELEMS];

__device__ __forceinline__ uint32_t smem_u32(const void* p) {
    uint32_t a;
    asm("{ .reg .u64 t; cvta.to.shared.u64 t, %1; cvt.u32.u64 %0, t; }"
        : "=r"(a) : "l"(p));
    return a;
}
__device__ __forceinline__ void cp16(uint32_t dst, const void* src) {
    asm volatile("cp.async.cg.shared.global [%0], [%1], 16;" :: "r"(dst), "l"(src));
}
__device__ __forceinline__ void cp_commit() {
    asm volatile("cp.async.commit_group;" ::);
}
template<int N>
__device__ __forceinline__ void cp_wait() {
    asm volatile("cp.async.wait_group %0;" :: "n"(N));
}
__device__ __forceinline__ void mma_f16(float* c, const uint32_t* a, const uint32_t* b) {
    asm volatile(
        "mma.sync.aligned.m16n8k16.row.col.f32.f16.f16.f32 "
        "{%0,%1,%2,%3}, {%4,%5,%6,%7}, {%8,%9}, {%0,%1,%2,%3};"
        : "+f"(c[0]), "+f"(c[1]), "+f"(c[2]), "+f"(c[3])
        : "r"(a[0]), "r"(a[1]), "r"(a[2]), "r"(a[3]), "r"(b[0]), "r"(b[1]));
}
__device__ __forceinline__ void ldm_x4(uint32_t* r, uint32_t addr) {
    asm volatile("ldmatrix.sync.aligned.m8n8.x4.shared.b16 {%0,%1,%2,%3}, [%4];"
                 : "=r"(r[0]), "=r"(r[1]), "=r"(r[2]), "=r"(r[3]) : "r"(addr));
}
__device__ __forceinline__ uint32_t pkh(float a, float b) {
    __half2 h = __floats2half2_rn(a, b);
    return *reinterpret_cast<uint32_t*>(&h);
}
__device__ __forceinline__ float gelu_f(float x) {
    const float c = 0.7978845608028654f;
    float x3 = x * x * x;
    return 0.5f * x * (1.0f + tanhf(c * (x + 0.044715f * x3)));
}

__global__ void embed_kernel(const int* __restrict__ tokens,
                             const float* __restrict__ we,
                             float* __restrict__ h)
{
    int t = blockIdx.x;
    int s = t % SS;
    int tok = tokens[t];
    const float* wrow = we + (size_t)tok * DD;
    const float* prow = we + (size_t)(VV + s) * DD;
    float* hrow = h + (size_t)t * DD;
    for (int i = threadIdx.x; i < DD; i += blockDim.x)
        hrow[i] = wrow[i] + prow[i];
}

// W[K,N] -> We[N,K]  (plain fp16 transpose)
__global__ __launch_bounds__(256)
void wexpand(const float* __restrict__ W, __half* __restrict__ We,
             int K, int N)
{
    __shared__ float t[32][33];
    const int n0 = blockIdx.x * 32;
    const int k0 = blockIdx.y * 32;
    const int tx = threadIdx.x & 31;
    const int ty = threadIdx.x >> 5;
    for (int r = ty; r < 32; r += 8)
        t[r][tx] = W[(size_t)(k0 + r) * N + n0 + tx];
    __syncthreads();
    for (int r = ty; r < 32; r += 8) {
        int n = n0 + r, k = k0 + tx;
        We[(size_t)n * K + k] = __float2half(t[tx][r]);
    }
}

// C[M,N] = X[M,K](fp32 -> fp16 on the fly) @ B[N,K]^T + bias
#define MSTAGES 4
#define APAD 40
#define ASTG (128 * APAD)
#define STG_ELEMS (2 * ASTG)
#define GEMM_SMEM (MSTAGES * STG_ELEMS * 2)

__global__ __launch_bounds__(256, 2)
void gemm_mma(const float* __restrict__ A, const __half* __restrict__ B,
              const float* __restrict__ bias, float* __restrict__ C,
              int N, int K, int act)
{
    extern __shared__ __half sh[];
    const int tid  = threadIdx.x;
    const int wid  = tid >> 5;
    const int lane = tid & 31;
    const int m0 = blockIdx.y * 128;
    const int n0 = blockIdx.x * 128;
    const int wm = (wid & 3) * 32;
    const int wn = (wid >> 2) * 64;
    const int nk = K >> 5;

    const float* Af = A + (size_t)m0 * K;
    const __half* Bb = B + (size_t)n0 * K;

    const int id0 = tid * 2, id1 = tid * 2 + 1;
    const int rb0 = id0 >> 2, cb0 = (id0 & 3) * 8;
    const int rb1 = id1 >> 2, cb1 = (id1 & 3) * 8;

    auto issueB = [&](int kc) {
        __half* Sb = sh + (kc & 3) * STG_ELEMS + ASTG;
        const __half* gb = Bb + (size_t)kc * 32;
        cp16(smem_u32(Sb + rb0 * APAD + cb0), gb + (size_t)rb0 * K + cb0);
        cp16(smem_u32(Sb + rb1 * APAD + cb1), gb + (size_t)rb1 * K + cb1);
        cp_commit();
    };

    int rA[4], cA[4];
    #pragma unroll
    for (int i = 0; i < 4; i++) {
        int idx = tid + i * 256;
        rA[i] = idx >> 3; cA[i] = (idx & 7) * 4;
    }
    float4 pa[4];
    auto ldA = [&](int kc) {
        const float* ap = Af + kc * 32;
        #pragma unroll
        for (int i = 0; i < 4; i++)
            pa[i] = *(const float4*)(ap + (size_t)rA[i] * K + cA[i]);
    };
    auto stsA = [&](int kc) {
        __half* Sa = sh + (kc & 3) * STG_ELEMS;
        #pragma unroll
        for (int i = 0; i < 4; i++) {
            uint2 w;
            w.x = pkh(pa[i].x, pa[i].y);
            w.y = pkh(pa[i].z, pa[i].w);
            *reinterpret_cast<uint2*>(Sa + rA[i] * APAD + cA[i]) = w;
        }
    };

    float acc[2][8][4];
    #pragma unroll
    for (int mt = 0; mt < 2; mt++)
        #pragma unroll
        for (int nt = 0; nt < 8; nt++)
            #pragma unroll
            for (int i = 0; i < 4; i++) acc[mt][nt][i] = 0.0f;

    issueB(0); issueB(1); issueB(2);
    ldA(0); stsA(0);
    ldA(1);
    cp_wait<2>();
    __syncthreads();

    for (int kc = 0; kc < nk; kc++) {
        if (kc + 1 < nk) stsA(kc + 1);
        if (kc + 2 < nk) ldA(kc + 2);
        if (kc + 3 < nk) issueB(kc + 3);

        const __half* Sa = sh + (kc & 3) * STG_ELEMS;
        const __half* Sb = Sa + ASTG;
        #pragma unroll
        for (int ks = 0; ks < 2; ks++) {
            const int kb = ks * 16;
            uint32_t af[2][4], bfr[8][2];
            #pragma unroll
            for (int mt = 0; mt < 2; mt++) {
                int row = wm + mt * 16 + (lane & 7) + ((lane >> 3) & 1) * 8;
                int col = kb + (lane >> 4) * 8;
                ldm_x4(af[mt], smem_u32(Sa + row * APAD + col));
            }
            #pragma unroll
            for (int np = 0; np < 4; np++) {
                int nt0 = np * 2;
                int row = wn + (nt0 + (lane >> 4)) * 8 + (lane & 7);
                int col = kb + ((lane >> 3) & 1) * 8;
                uint32_t r4[4];
                ldm_x4(r4, smem_u32(Sb + row * APAD + col));
                bfr[nt0][0] = r4[0]; bfr[nt0][1] = r4[1];
                bfr[nt0 + 1][0] = r4[2]; bfr[nt0 + 1][1] = r4[3];
            }
            #pragma unroll
            for (int mt = 0; mt < 2; mt++)
                #pragma unroll
                for (int nt = 0; nt < 8; nt++)
                    mma_f16(acc[mt][nt], af[mt], bfr[nt]);
        }
        if (kc + 1 < nk) { cp_wait<2>(); __syncthreads(); }
    }

    #pragma unroll
    for (int mt = 0; mt < 2; mt++) {
        const int r = m0 + wm + mt * 16 + (lane >> 2);
        #pragma unroll
        for (int nt = 0; nt < 8; nt++) {
            const int c = n0 + wn + nt * 8 + (lane & 3) * 2;
            const float b0 = bias[c], b1 = bias[c + 1];
            float v0 = acc[mt][nt][0] + b0;
            float v1 = acc[mt][nt][1] + b1;
            float v2 = acc[mt][nt][2] + b0;
            float v3 = acc[mt][nt][3] + b1;
            if (act) { v0 = gelu_f(v0); v1 = gelu_f(v1); v2 = gelu_f(v2); v3 = gelu_f(v3); }
            *(float2*)(C + (size_t)r * N + c)       = make_float2(v0, v1);
            *(float2*)(C + (size_t)(r + 8) * N + c) = make_float2(v2, v3);
        }
    }
}

// ---------------- fp16 tensor-core flash attention (proven core) -----------
#define QSTR 72

__global__ __launch_bounds__(256)
void attn_mma(const float* __restrict__ qkv, float* __restrict__ out)
{
    __shared__ __half Qs[128 * QSTR];
    __shared__ __half Ks[64 * QSTR];
    __shared__ __half Vt[64 * QSTR];

    const int tid = threadIdx.x;
    const int wid = tid >> 5;
    const int lane = tid & 31;
    const int qt = blockIdx.x;
    const int h  = blockIdx.y;
    const int b  = blockIdx.z;
    const int wq0 = wid * 16;
    const float* base = qkv + (size_t)b * SS * (3 * DD);

    #pragma unroll
    for (int t = 0; t < 8; t++) {
        int li = tid + t * 256;
        int row = li >> 4, d4 = (li & 15) * 4;
        float4 v = *(const float4*)(base + (size_t)(qt * 128 + row) * (3 * DD) + h * 64 + d4);
        uint2 w;
        w.x = pkh(v.x * 0.125f, v.y * 0.125f);
        w.y = pkh(v.z * 0.125f, v.w * 0.125f);
        *reinterpret_cast<uint2*>(Qs + row * QSTR + d4) = w;
    }

    float m0 = -1e30f, m1 = -1e30f, l0 = 0.0f, l1 = 0.0f;
    float oacc[8][4];
    #pragma unroll
    for (int nf = 0; nf < 8; nf++)
        #pragma unroll
        for (int j = 0; j < 4; j++) oacc[nf][j] = 0.0f;

    const int nkt = 2 * (qt + 1);
    for (int kt = 0; kt < nkt; kt++) {
        __syncthreads();
        #pragma unroll
        for (int t = 0; t < 4; t++) {
            int li = tid + t * 256;
            int tok = li >> 4, d4 = (li & 15) * 4;
            const float* kp = base + (size_t)(kt * 64 + tok) * (3 * DD) + DD + h * 64 + d4;
            float4 kv = *(const float4*)kp;
            uint2 w;
            w.x = pkh(kv.x, kv.y);
            w.y = pkh(kv.z, kv.w);
            *reinterpret_cast<uint2*>(Ks + tok * QSTR + d4) = w;
            float4 vv = *(const float4*)(kp + DD);
            Vt[(d4 + 0) * QSTR + tok] = __float2half(vv.x);
            Vt[(d4 + 1) * QSTR + tok] = __float2half(vv.y);
            Vt[(d4 + 2) * QSTR + tok] = __float2half(vv.z);
            Vt[(d4 + 3) * QSTR + tok] = __float2half(vv.w);
        }
        __syncthreads();

        float sacc[8][4];
        #pragma unroll
        for (int nf = 0; nf < 8; nf++)
            #pragma unroll
            for (int j = 0; j < 4; j++) sacc[nf][j] = 0.0f;

        const int arow = wq0 + (lane & 15);
        const int brow = (lane >> 4) * 8 + (lane & 7);
        #pragma unroll
        for (int kf = 0; kf < 4; kf++) {
            uint32_t aq[4];
            ldm_x4(aq, smem_u32(Qs + arow * QSTR + kf * 16 + (lane >> 4) * 8));
            const int bcol = kf * 16 + ((lane >> 3) & 1) * 8;
            #pragma unroll
            for (int g = 0; g < 4; g++) {
                uint32_t r4[4];
                ldm_x4(r4, smem_u32(Ks + (g * 16 + brow) * QSTR + bcol));
                uint32_t b0[2] = {r4[0], r4[1]}, b1[2] = {r4[2], r4[3]};
                mma_f16(sacc[2 * g],     aq, b0);
                mma_f16(sacc[2 * g + 1], aq, b1);
            }
        }

        if (kt >= 2 * qt) {
            const int r0g = qt * 128 + wq0 + (lane >> 2);
            const int r1g = r0g + 8;
            #pragma unroll
            for (int nf = 0; nf < 8; nf++) {
                int cg = kt * 64 + nf * 8 + (lane & 3) * 2;
                if (cg     > r0g) sacc[nf][0] = -1e9f;
                if (cg + 1 > r0g) sacc[nf][1] = -1e9f;
                if (cg     > r1g) sacc[nf][2] = -1e9f;
                if (cg + 1 > r1g) sacc[nf][3] = -1e9f;
            }
        }

        float mx0 = -1e30f, mx1 = -1e30f;
        #pragma unroll
        for (int nf = 0; nf < 8; nf++) {
            mx0 = fmaxf(mx0, fmaxf(sacc[nf][0], sacc[nf][1]));
            mx1 = fmaxf(mx1, fmaxf(sacc[nf][2], sacc[nf][3]));
        }
        mx0 = fmaxf(mx0, __shfl_xor_sync(0xffffffffu, mx0, 1));
        mx0 = fmaxf(mx0, __shfl_xor_sync(0xffffffffu, mx0, 2));
        mx1 = fmaxf(mx1, __shfl_xor_sync(0xffffffffu, mx1, 1));
        mx1 = fmaxf(mx1, __shfl_xor_sync(0xffffffffu, mx1, 2));
        float mn0 = fmaxf(m0, mx0), mn1 = fmaxf(m1, mx1);
        float a0 = __expf(m0 - mn0), a1 = __expf(m1 - mn1);
        m0 = mn0; m1 = mn1;

        float rs0 = 0.0f, rs1 = 0.0f;
        #pragma unroll
        for (int nf = 0; nf < 8; nf++) {
            sacc[nf][0] = __expf(sacc[nf][0] - m0);
            sacc[nf][1] = __expf(sacc[nf][1] - m0);
            sacc[nf][2] = __expf(sacc[nf][2] - m1);
            sacc[nf][3] = __expf(sacc[nf][3] - m1);
            rs0 += sacc[nf][0] + sacc[nf][1];
            rs1 += sacc[nf][2] + sacc[nf][3];
        }
        rs0 += __shfl_xor_sync(0xffffffffu, rs0, 1);
        rs0 += __shfl_xor_sync(0xffffffffu, rs0, 2);
        rs1 += __shfl_xor_sync(0xffffffffu, rs1, 1);
        rs1 += __shfl_xor_sync(0xffffffffu, rs1, 2);
        l0 = l0 * a0 + rs0;
        l1 = l1 * a1 + rs1;
        #pragma unroll
        for (int nf = 0; nf < 8; nf++) {
            oacc[nf][0] *= a0; oacc[nf][1] *= a0;
            oacc[nf][2] *= a1; oacc[nf][3] *= a1;
        }

        #pragma unroll
        for (int kf = 0; kf < 4; kf++) {
            uint32_t ap[4];
            ap[0] = pkh(sacc[2 * kf][0],     sacc[2 * kf][1]);
            ap[1] = pkh(sacc[2 * kf][2],     sacc[2 * kf][3]);
            ap[2] = pkh(sacc[2 * kf + 1][0], sacc[2 * kf + 1][1]);
            ap[3] = pkh(sacc[2 * kf + 1][2], sacc[2 * kf + 1][3]);
            const int bcol = kf * 16 + ((lane >> 3) & 1) * 8;
            #pragma unroll
            for (int g = 0; g < 4; g++) {
                uint32_t r4[4];
                ldm_x4(r4, smem_u32(Vt + (g * 16 + brow) * QSTR + bcol));
                uint32_t b0[2] = {r4[0], r4[1]}, b1[2] = {r4[2], r4[3]};
                mma_f16(oacc[2 * g],     ap, b0);
                mma_f16(oacc[2 * g + 1], ap, b1);
            }
        }
    }

    const float inv0 = 1.0f / l0, inv1 = 1.0f / l1;
    const int rg = b * SS + qt * 128 + wq0 + (lane >> 2);
    #pragma unroll
    for (int nf = 0; nf < 8; nf++) {
        const int c = h * 64 + nf * 8 + (lane & 3) * 2;
        *(float2*)(out + (size_t)rg * DD + c) =
            make_float2(oacc[nf][0] * inv0, oacc[nf][1] * inv0);
        *(float2*)(out + (size_t)(rg + 8) * DD + c) =
            make_float2(oacc[nf][2] * inv1, oacc[nf][3] * inv1);
    }
}

__global__ __launch_bounds__(256)
void add_ln_kernel(const float* __restrict__ x, const float* __restrict__ a,
                   const float* __restrict__ g, const float* __restrict__ bb,
                   float* __restrict__ out)
{
    const int row = blockIdx.x;
    const int tid = threadIdx.x;
    __shared__ float red[256];

    const size_t off = (size_t)row * DD;
    float v[3];
    float s = 0.0f;
    #pragma unroll
    for (int i = 0; i < 3; i++) {
        int c = tid + 256 * i;
        v[i] = x[off + c] + a[off + c];
        s += v[i];
    }
    red[tid] = s; __syncthreads();
    for (int st = 128; st > 0; st >>= 1) {
        if (tid < st) red[tid] += red[tid + st];
        __syncthreads();
    }
    const float mean = red[0] * (1.0f / DD);
    __syncthreads();

    float s2 = 0.0f;
    #pragma unroll
    for (int i = 0; i < 3; i++) {
        float d = v[i] - mean;
        s2 += d * d;
    }
    red[tid] = s2; __syncthreads();
    for (int st = 128; st > 0; st >>= 1) {
        if (tid < st) red[tid] += red[tid + st];
        __syncthreads();
    }
    const float inv = rsqrtf(red[0] * (1.0f / DD) + 1e-5f);

    #pragma unroll
    for (int i = 0; i < 3; i++) {
        int c = tid + 256 * i;
        out[off + c] = g[c] * (v[i] - mean) * inv + bb[c];
    }
}

extern "C" void kernel_launch(void* const* d_in, const int* in_sizes, int n_in,
                              void* d_out, int out_size)
{
    const int*   tokens = (const int*)  d_in[0];
    const float* we     = (const float*)d_in[1];
    const float* wqkv   = (const float*)d_in[2];
    const float* bqkv   = (const float*)d_in[3];
    const float* wproj  = (const float*)d_in[4];
    const float* bproj  = (const float*)d_in[5];
    const float* g1     = (const float*)d_in[6];
    const float* b1     = (const float*)d_in[7];
    const float* wfc    = (const float*)d_in[8];
    const float* bfc    = (const float*)d_in[9];
    const float* wpr    = (const float*)d_in[10];
    const float* bpr    = (const float*)d_in[11];
    const float* g2     = (const float*)d_in[12];
    const float* b2     = (const float*)d_in[13];
    float* out = (float*)d_out;

    float *h, *qkv, *attn, *tmp, *mid;
    __half *wex;
    cudaGetSymbolAddress((void**)&h,    g_h);
    cudaGetSymbolAddress((void**)&qkv,  g_qkv);
    cudaGetSymbolAddress((void**)&attn, g_attn);
    cudaGetSymbolAddress((void**)&tmp,  g_tmp);
    cudaGetSymbolAddress((void**)&mid,  g_mid);
    cudaGetSymbolAddress((void**)&wex,  g_wexp);

    cudaFuncSetAttribute(gemm_mma, cudaFuncAttributeMaxDynamicSharedMemorySize, GEMM_SMEM);

    for (int l = 0; l < LL; l++) {
        __half* wl = wex + (size_t)l * WL_ELEMS;
        wexpand<<<dim3(3*DD/32, DD/32), 256>>>(wqkv  + (size_t)l*DD*3*DD, wl + OFF_Q, DD, 3*DD);
        wexpand<<<dim3(DD/32,   DD/32), 256>>>(wproj + (size_t)l*DD*DD,   wl + OFF_P, DD, DD);
        wexpand<<<dim3(DF/32,   DD/32), 256>>>(wfc   + (size_t)l*DD*DF,   wl + OFF_F, DD, DF);
        wexpand<<<dim3(DD/32,   DF/32), 256>>>(wpr   + (size_t)l*DF*DD,   wl + OFF_R, DF, DD);
    }

    embed_kernel<<<MTOK, 256>>>(tokens, we, h);

    for (int l = 0; l < LL; l++) {
        const __half* wl = wex + (size_t)l * WL_ELEMS;
        const float* bq = bqkv  + (size_t)l * 3 * DD;
        const float* bp = bproj + (size_t)l * DD;
        const float* gA = g1 + (size_t)l * DD;
        const float* bA = b1 + (size_t)l * DD;
        const float* bf = bfc + (size_t)l * DF;
        const float* br = bpr + (size_t)l * DD;
        const float* gB = g2 + (size_t)l * DD;
        const float* bB = b2 + (size_t)l * DD;

        gemm_mma<<<dim3(3*DD/128, MTOK/128), 256, GEMM_SMEM>>>(
            h, wl + OFF_Q, bq, qkv, 3*DD, DD, 0);

        attn_mma<<<dim3(4, HH, BB), 256>>>(qkv, attn);

        gemm_mma<<<dim3(DD/128, MTOK/128), 256, GEMM_SMEM>>>(
            attn, wl + OFF_P, bp, tmp, DD, DD, 0);

        add_ln_kernel<<<MTOK, 256>>>(h, tmp, gA, bA, h);

        gemm_mma<<<dim3(DF/128, MTOK/128), 256, GEMM_SMEM>>>(
            h, wl + OFF_F, bf, mid, DF, DD, 1);

        gemm_mma<<<dim3(DD/128, MTOK/128), 256, GEMM_SMEM>>>(
            mid, wl + OFF_R, br, tmp, DD, DF, 0);

        float* o = (l == LL - 1) ? out : h;
        add_ln_kernel<<<MTOK, 256>>>(h, tmp, gB, bB, o);
    }
}